// round 10
// baseline (speedup 1.0000x reference)
#include <cuda_runtime.h>

// LiftSplatBEV — fixed shapes
// feat_bn   : [12, 64, 112, 200] f32
// depth_prob: [12, 64, 112, 200] f32
// I_inv     : [2, 6, 3, 3] f32
// E_inv     : [2, 6, 4, 4] f32
// V         : [3, 3] f32
// out       : [2, 64, 200, 200] f32

static constexpr int B_   = 2;
static constexpr int N_   = 6;
static constexpr int C_   = 64;
static constexpr int HF_  = 112;
static constexpr int WF_  = 200;
static constexpr int D_   = 64;
static constexpr int HWP  = HF_ * WF_;     // 22400
static constexpr int BEVH = 200;
static constexpr int BEVW = 200;
static constexpr int HWB  = BEVH * BEVW;   // 40000

// Accumulator scratch: [b][bev_cell][channel]  (channel contiguous -> v4 atomics)
// Zero at module load; k_transpose re-zeroes after reading, so the invariant
// "scratch is zero when k_scatter starts" holds across graph replays.
__device__ float g_scratch[(size_t)B_ * HWB * C_];

__device__ __forceinline__ void red4(float* a, float4 v) {
    asm volatile("red.global.add.v4.f32 [%0], {%1,%2,%3,%4};"
                 :: "l"(a), "f"(v.x), "f"(v.y), "f"(v.z), "f"(v.w)
                 : "memory");
}

#define PACK2(dst, lo, hi) \
    asm("mov.b64 %0, {%1, %2};" : "=l"(dst) : "f"(lo), "f"(hi))
#define UNPACK2(lo, hi, src) \
    asm("mov.b64 {%0, %1}, %2;" : "=f"(lo), "=f"(hi) : "l"(src))
#define MUL2(d, a, b) \
    asm("mul.rn.f32x2 %0, %1, %2;" : "=l"(d) : "l"(a), "l"(b))
#define ADD2(d, a, b) \
    asm("add.rn.f32x2 %0, %1, %2;" : "=l"(d) : "l"(a), "l"(b))

__global__ __launch_bounds__(224)
void k_scatter(const float* __restrict__ feat,
               const float* __restrict__ depth,
               const float* __restrict__ I_inv,
               const float* __restrict__ E_inv,
               const float* __restrict__ Vm) {
    const int p    = blockIdx.x * blockDim.x + threadIdx.x;   // 100*224 == 22400
    const int bn   = blockIdx.y;
    const int lane = threadIdx.x & 31;
    const unsigned FULL = 0xffffffffu;

    // ---- geometry (bug-faithful: grid flattened width-outer) ----
    const float u = (float)(p / HF_);     // image x (width index)
    const float v = (float)(p % HF_);     // image y (height index)

    const float* Ii = I_inv + bn * 9;
    const float* Ei = E_inv + bn * 16;

    const float cx = Ii[0] * u + Ii[1] * v + Ii[2];
    const float cy = Ii[3] * u + Ii[4] * v + Ii[5];
    const float cz = Ii[6] * u + Ii[7] * v + Ii[8];

    const float tx = Ei[3], ty = Ei[7], tz = Ei[11];
    // reference keeps the +t in the "direction" (d = E_inv @ [cam;1])
    const float dx = Ei[0] * cx + Ei[1] * cy + Ei[2]  * cz + tx;
    const float dy = Ei[4] * cx + Ei[5] * cy + Ei[6]  * cz + ty;
    const float dz = Ei[8] * cx + Ei[9] * cy + Ei[10] * cz + tz;

    const float s  = -tz / fmaxf(dz, 1e-6f);
    const float ex = tx + dx * s;
    const float ey = ty + dy * s;

    const float p0 = Vm[0] * ex + Vm[1] * ey + Vm[2];
    const float p1 = Vm[3] * ex + Vm[4] * ey + Vm[5];
    const float p2 = Vm[6] * ex + Vm[7] * ey + Vm[8];
    const float zc = fmaxf(p2, 1e-7f);
    const float bevx = p0 / zc;
    const float bevy = p1 / zc;

    // gx/px round-trip (replicate reference float ops)
    const float gx = bevx / (float)(BEVW - 1) * 2.f - 1.f;
    const float gy = bevy / (float)(BEVH - 1) * 2.f - 1.f;
    const float px = (gx + 1.f) * (float)(BEVW - 1) / 2.f;
    const float py = (gy + 1.f) * (float)(BEVH - 1) / 2.f;

    const float x0 = fminf(fmaxf(floorf(px), 0.f), (float)(BEVW - 1));
    const float y0 = fminf(fmaxf(floorf(py), 0.f), (float)(BEVH - 1));
    const float x1 = fminf(x0 + 1.f, (float)(BEVW - 1));
    const float y1 = fminf(y0 + 1.f, (float)(BEVH - 1));

    // ---- conf = max_d depth_prob[bn, d, p] ----
    const float* dp = depth + (size_t)bn * D_ * HWP + p;
    float conf = dp[0];
    #pragma unroll 8
    for (int d = 1; d < D_; d++)
        conf = fmaxf(conf, dp[(size_t)d * HWP]);

    const float scale = conf * (1.f / (float)N_);   // fold mean over n

    float ws[4];
    ws[0] = (x1 - px) * (y1 - py) * scale;
    ws[1] = (px - x0) * (y1 - py) * scale;
    ws[2] = (x1 - px) * (py - y0) * scale;
    ws[3] = (px - x0) * (py - y0) * scale;

    int idxs[4];
    idxs[0] = (int)y0 * BEVW + (int)x0;
    idxs[1] = (int)y0 * BEVW + (int)x1;
    idxs[2] = (int)y1 * BEVW + (int)x0;
    idxs[3] = (int)y1 * BEVW + (int)x1;

    // ---- shared segmented-run structure (from i00 only) ----
    // i00 = y0*200+x0 uniquely determines (x0,y0), and every corner index is a
    // deterministic function of (x0,y0). So segments of equal i00 imply equal
    // idxs[k] for all k -> ONE segmentation serves all four corners
    // (conservative: distinct i00 with coincidentally equal i10 just issue
    // separate reds, still correct).
    // Segments defined by head flags => contiguous by construction.
    unsigned cond;      // bit st: legal to fold in lane+2^st (same segment)
    bool     head;      // lane is first lane of its segment (issues the red)
    unsigned stepm;     // warp-uniform: any lane needs step st
    {
        const int id = idxs[0];
        const int up = __shfl_up_sync(FULL, id, 1);
        head = (lane == 0) || (up != id);
        const unsigned hbm = __ballot_sync(FULL, head);
        const unsigned long long above = (unsigned long long)hbm >> (lane + 1);
        unsigned cm = 0;
        #pragma unroll
        for (int st = 0; st < 5; st++) {
            const int off = 1 << st;
            if ((lane + off < 32) &&
                ((above & (unsigned long long)((1u << off) - 1u)) == 0ull))
                cm |= (1u << st);
        }
        cond = cm;
        unsigned sm = 0;
        #pragma unroll
        for (int st = 0; st < 5; st++)
            if (__any_sync(FULL, cm & (1u << st))) sm |= (1u << st);
        stepm = sm;
    }

    float* sb = g_scratch + (size_t)(bn / N_) * HWB * C_;
    const float* fp = feat + (size_t)bn * C_ * HWP + p;

    // packed duplicate weights (w,w) for f32x2 math
    unsigned long long wp[4];
    #pragma unroll
    for (int k = 0; k < 4; k++) PACK2(wp[k], ws[k], ws[k]);

    float* base[4];
    #pragma unroll
    for (int k = 0; k < 4; k++) base[k] = sb + (size_t)idxs[k] * C_;

    #pragma unroll 2
    for (int c = 0; c < C_; c += 4) {
        float4 f;
        f.x = __ldg(fp + (size_t)(c + 0) * HWP);
        f.y = __ldg(fp + (size_t)(c + 1) * HWP);
        f.z = __ldg(fp + (size_t)(c + 2) * HWP);
        f.w = __ldg(fp + (size_t)(c + 3) * HWP);
        unsigned long long f01, f23;
        PACK2(f01, f.x, f.y);
        PACK2(f23, f.z, f.w);

        #pragma unroll
        for (int k = 0; k < 4; k++) {
            unsigned long long v01, v23;
            MUL2(v01, f01, wp[k]);
            MUL2(v23, f23, wp[k]);

            if (stepm) {
                // segmented suffix-sum: head lane ends with its segment total
                #pragma unroll
                for (int st = 0; st < 5; st++) {
                    if (stepm & (1u << st)) {   // warp-uniform
                        const int off = 1 << st;
                        float a, b2, c2, d2;
                        UNPACK2(a, b2, v01);
                        UNPACK2(c2, d2, v23);
                        const float oa = __shfl_down_sync(FULL, a,  off);
                        const float ob = __shfl_down_sync(FULL, b2, off);
                        const float oc = __shfl_down_sync(FULL, c2, off);
                        const float od = __shfl_down_sync(FULL, d2, off);
                        unsigned long long o01, o23;
                        PACK2(o01, oa, ob);
                        PACK2(o23, oc, od);
                        if (cond & (1u << st)) {
                            ADD2(v01, v01, o01);
                            ADD2(v23, v23, o23);
                        }
                    }
                }
                if (head) {
                    float a, b2, c2, d2;
                    UNPACK2(a, b2, v01);
                    UNPACK2(c2, d2, v23);
                    red4(base[k] + c, make_float4(a, b2, c2, d2));
                }
            } else {
                float a, b2, c2, d2;
                UNPACK2(a, b2, v01);
                UNPACK2(c2, d2, v23);
                red4(base[k] + c, make_float4(a, b2, c2, d2));
            }
        }
    }
}

// scratch [b][cell][c] -> out [b][c][cell], tiled transpose.
// Also re-zeroes scratch (each element read exactly once) so the next
// graph replay's k_scatter starts from a clean accumulator.
__global__ __launch_bounds__(256)
void k_transpose(float* __restrict__ out) {
    __shared__ float tile[32][33];
    const int cellBase = blockIdx.x * 32;   // 40000 / 32 = 1250 exact
    const int cBase    = blockIdx.y * 32;   // 64 / 32 = 2
    const int b        = blockIdx.z;
    const int tx = threadIdx.x;             // 0..31
    const int ty = threadIdx.y;             // 0..7

    float* src = g_scratch + (size_t)b * HWB * C_;
    #pragma unroll
    for (int r = 0; r < 4; r++) {
        int cell = cellBase + ty + r * 8;
        float* sp = src + (size_t)cell * C_ + cBase + tx;
        tile[ty + r * 8][tx] = *sp;
        *sp = 0.f;                          // re-zero for next replay
    }
    __syncthreads();
    #pragma unroll
    for (int r = 0; r < 4; r++) {
        int ch = cBase + ty + r * 8;
        out[((size_t)b * C_ + ch) * HWB + cellBase + tx] = tile[tx][ty + r * 8];
    }
}

extern "C" void kernel_launch(void* const* d_in, const int* in_sizes, int n_in,
                              void* d_out, int out_size) {
    const float* feat  = (const float*)d_in[0];
    const float* depth = (const float*)d_in[1];
    const float* I_inv = (const float*)d_in[2];
    const float* E_inv = (const float*)d_in[3];
    const float* Vm    = (const float*)d_in[4];
    float* out = (float*)d_out;

    dim3 gs(HWP / 224, B_ * N_);   // (100, 12)
    k_scatter<<<gs, 224>>>(feat, depth, I_inv, E_inv, Vm);

    dim3 gt(HWB / 32, C_ / 32, B_);  // (1250, 2, 2)
    dim3 bt(32, 8);
    k_transpose<<<gt, bt>>>(out);
}

// round 11
// speedup vs baseline: 1.3336x; 1.3336x over previous
#include <cuda_runtime.h>

// LiftSplatBEV — fixed shapes
// feat_bn   : [12, 64, 112, 200] f32
// depth_prob: [12, 64, 112, 200] f32
// I_inv     : [2, 6, 3, 3] f32
// E_inv     : [2, 6, 4, 4] f32
// V         : [3, 3] f32
// out       : [2, 64, 200, 200] f32

static constexpr int B_   = 2;
static constexpr int N_   = 6;
static constexpr int C_   = 64;
static constexpr int HF_  = 112;
static constexpr int WF_  = 200;
static constexpr int D_   = 64;
static constexpr int HWP  = HF_ * WF_;     // 22400
static constexpr int BEVH = 200;
static constexpr int BEVW = 200;
static constexpr int HWB  = BEVH * BEVW;   // 40000

// Accumulator scratch: [b][bev_cell][channel]  (channel contiguous -> v4 atomics)
// Zero at module load; k_transpose re-zeroes (vectorized) after reading, so
// "scratch is zero when k_scatter starts" holds across graph replays.
__device__ float g_scratch[(size_t)B_ * HWB * C_];

__device__ __forceinline__ void red4(float* a, float4 v) {
    asm volatile("red.global.add.v4.f32 [%0], {%1,%2,%3,%4};"
                 :: "l"(a), "f"(v.x), "f"(v.y), "f"(v.z), "f"(v.w)
                 : "memory");
}

__global__ __launch_bounds__(224)
void k_scatter(const float* __restrict__ feat,
               const float* __restrict__ depth,
               const float* __restrict__ I_inv,
               const float* __restrict__ E_inv,
               const float* __restrict__ Vm) {
    const int p    = blockIdx.x * blockDim.x + threadIdx.x;   // 100*224 == 22400
    const int bn   = blockIdx.y;
    const int lane = threadIdx.x & 31;
    const unsigned FULL = 0xffffffffu;

    // ---- geometry (bug-faithful: grid flattened width-outer) ----
    const float u = (float)(p / HF_);     // image x (width index)
    const float v = (float)(p % HF_);     // image y (height index)

    const float* Ii = I_inv + bn * 9;
    const float* Ei = E_inv + bn * 16;

    const float cx = Ii[0] * u + Ii[1] * v + Ii[2];
    const float cy = Ii[3] * u + Ii[4] * v + Ii[5];
    const float cz = Ii[6] * u + Ii[7] * v + Ii[8];

    const float tx = Ei[3], ty = Ei[7], tz = Ei[11];
    // reference keeps the +t in the "direction" (d = E_inv @ [cam;1])
    const float dx = Ei[0] * cx + Ei[1] * cy + Ei[2]  * cz + tx;
    const float dy = Ei[4] * cx + Ei[5] * cy + Ei[6]  * cz + ty;
    const float dz = Ei[8] * cx + Ei[9] * cy + Ei[10] * cz + tz;

    const float s  = -tz / fmaxf(dz, 1e-6f);
    const float ex = tx + dx * s;
    const float ey = ty + dy * s;

    const float p0 = Vm[0] * ex + Vm[1] * ey + Vm[2];
    const float p1 = Vm[3] * ex + Vm[4] * ey + Vm[5];
    const float p2 = Vm[6] * ex + Vm[7] * ey + Vm[8];
    const float zc = fmaxf(p2, 1e-7f);
    const float bevx = p0 / zc;
    const float bevy = p1 / zc;

    // gx/px round-trip (replicate reference float ops)
    const float gx = bevx / (float)(BEVW - 1) * 2.f - 1.f;
    const float gy = bevy / (float)(BEVH - 1) * 2.f - 1.f;
    const float px = (gx + 1.f) * (float)(BEVW - 1) / 2.f;
    const float py = (gy + 1.f) * (float)(BEVH - 1) / 2.f;

    const float x0 = fminf(fmaxf(floorf(px), 0.f), (float)(BEVW - 1));
    const float y0 = fminf(fmaxf(floorf(py), 0.f), (float)(BEVH - 1));
    const float x1 = fminf(x0 + 1.f, (float)(BEVW - 1));
    const float y1 = fminf(y0 + 1.f, (float)(BEVH - 1));

    // ---- conf = max_d depth_prob[bn, d, p] ----
    const float* dp = depth + (size_t)bn * D_ * HWP + p;
    float conf = dp[0];
    #pragma unroll 8
    for (int d = 1; d < D_; d++)
        conf = fmaxf(conf, dp[(size_t)d * HWP]);

    const float scale = conf * (1.f / (float)N_);   // fold mean over n

    float ws[4];
    ws[0] = (x1 - px) * (y1 - py) * scale;
    ws[1] = (px - x0) * (y1 - py) * scale;
    ws[2] = (x1 - px) * (py - y0) * scale;
    ws[3] = (px - x0) * (py - y0) * scale;

    int idxs[4];
    idxs[0] = (int)y0 * BEVW + (int)x0;
    idxs[1] = (int)y0 * BEVW + (int)x1;
    idxs[2] = (int)y1 * BEVW + (int)x0;
    idxs[3] = (int)y1 * BEVW + (int)x1;

    // ---- shared segmented-run structure (from i00 only) ----
    // i00 = y0*200+x0 uniquely determines (x0,y0); every corner index is a
    // deterministic function of (x0,y0), so one segmentation serves all four
    // corners (conservative for coincidental equality across different i00).
    // Segments defined by head flags => contiguous by construction.
    unsigned cond;      // bit st: legal to fold in lane+2^st (same segment)
    bool     head;      // lane is first lane of its segment (issues the red)
    unsigned stepm;     // warp-uniform: any lane needs step st
    {
        const int id = idxs[0];
        const int up = __shfl_up_sync(FULL, id, 1);
        head = (lane == 0) || (up != id);
        const unsigned hbm = __ballot_sync(FULL, head);
        const unsigned long long above = (unsigned long long)hbm >> (lane + 1);
        unsigned cm = 0;
        #pragma unroll
        for (int st = 0; st < 5; st++) {
            const int off = 1 << st;
            if ((lane + off < 32) &&
                ((above & (unsigned long long)((1u << off) - 1u)) == 0ull))
                cm |= (1u << st);
        }
        cond = cm;
        unsigned sm = 0;
        #pragma unroll
        for (int st = 0; st < 5; st++)
            if (__any_sync(FULL, cm & (1u << st))) sm |= (1u << st);
        stepm = sm;
    }

    float* sb = g_scratch + (size_t)(bn / N_) * HWB * C_;
    const float* fp = feat + (size_t)bn * C_ * HWP + p;

    float* base[4];
    #pragma unroll
    for (int k = 0; k < 4; k++) base[k] = sb + (size_t)idxs[k] * C_;

    #pragma unroll 2
    for (int c = 0; c < C_; c += 4) {
        float4 f;
        f.x = __ldg(fp + (size_t)(c + 0) * HWP);
        f.y = __ldg(fp + (size_t)(c + 1) * HWP);
        f.z = __ldg(fp + (size_t)(c + 2) * HWP);
        f.w = __ldg(fp + (size_t)(c + 3) * HWP);

        #pragma unroll
        for (int k = 0; k < 4; k++) {
            float4 vv = make_float4(f.x * ws[k], f.y * ws[k],
                                    f.z * ws[k], f.w * ws[k]);
            if (stepm) {
                // segmented suffix-sum: head lane ends with its segment total
                #pragma unroll
                for (int st = 0; st < 5; st++) {
                    if (stepm & (1u << st)) {   // warp-uniform
                        const int off = 1 << st;
                        float ox = __shfl_down_sync(FULL, vv.x, off);
                        float oy = __shfl_down_sync(FULL, vv.y, off);
                        float oz = __shfl_down_sync(FULL, vv.z, off);
                        float ow = __shfl_down_sync(FULL, vv.w, off);
                        if (cond & (1u << st)) {
                            vv.x += ox; vv.y += oy; vv.z += oz; vv.w += ow;
                        }
                    }
                }
                if (head)
                    red4(base[k] + c, vv);
            } else {
                red4(base[k] + c, vv);
            }
        }
    }
}

// scratch [b][cell][c] -> out [b][c][cell], 64x64 tiles, fully vectorized
// global accesses (LDG.128 / STG.128). Also re-zeroes scratch (vectorized)
// for the next graph replay.
__global__ __launch_bounds__(256)
void k_transpose(float* __restrict__ out) {
    __shared__ float tile[C_][65];          // [channel][cell], pad 65: <=2-way
    const int cellBase = blockIdx.x * 64;   // 40000 / 64 = 625 exact
    const int b        = blockIdx.y;
    const int t        = threadIdx.x;       // 0..255

    float* src = g_scratch + (size_t)b * HWB * C_;

    // load: 64 cells x 64 ch; thread t, iter r: cell = (t>>4) + 16r, c = (t&15)*4
    const int cgrp = (t & 15) * 4;
    const int crow = t >> 4;                // 0..15
    #pragma unroll
    for (int r = 0; r < 4; r++) {
        const int cell = crow + 16 * r;
        float4* sp = reinterpret_cast<float4*>(
            src + (size_t)(cellBase + cell) * C_ + cgrp);
        const float4 f = *sp;
        tile[cgrp + 0][cell] = f.x;
        tile[cgrp + 1][cell] = f.y;
        tile[cgrp + 2][cell] = f.z;
        tile[cgrp + 3][cell] = f.w;
        *sp = make_float4(0.f, 0.f, 0.f, 0.f);   // re-zero for next replay
    }
    __syncthreads();

    // store: thread t, iter r: ch = (t>>4) + 16r, cells (t&15)*4 .. +3
    #pragma unroll
    for (int r = 0; r < 4; r++) {
        const int ch = crow + 16 * r;
        const float4 o = make_float4(tile[ch][cgrp + 0], tile[ch][cgrp + 1],
                                     tile[ch][cgrp + 2], tile[ch][cgrp + 3]);
        *reinterpret_cast<float4*>(
            out + ((size_t)b * C_ + ch) * HWB + cellBase + cgrp) = o;
    }
}

extern "C" void kernel_launch(void* const* d_in, const int* in_sizes, int n_in,
                              void* d_out, int out_size) {
    const float* feat  = (const float*)d_in[0];
    const float* depth = (const float*)d_in[1];
    const float* I_inv = (const float*)d_in[2];
    const float* E_inv = (const float*)d_in[3];
    const float* Vm    = (const float*)d_in[4];
    float* out = (float*)d_out;

    dim3 gs(HWP / 224, B_ * N_);   // (100, 12)
    k_scatter<<<gs, 224>>>(feat, depth, I_inv, E_inv, Vm);

    dim3 gt(HWB / 64, B_);         // (625, 2)
    k_transpose<<<gt, 256>>>(out);
}

// round 13
// speedup vs baseline: 2.0841x; 1.5627x over previous
#include <cuda_runtime.h>

// LiftSplatBEV — fixed shapes
// feat_bn   : [12, 64, 112, 200] f32
// depth_prob: [12, 64, 112, 200] f32
// I_inv     : [2, 6, 3, 3] f32
// E_inv     : [2, 6, 4, 4] f32
// V         : [3, 3] f32
// out       : [2, 64, 200, 200] f32

static constexpr int B_   = 2;
static constexpr int N_   = 6;
static constexpr int C_   = 64;
static constexpr int HF_  = 112;
static constexpr int WF_  = 200;
static constexpr int D_   = 64;
static constexpr int HWP  = HF_ * WF_;     // 22400
static constexpr int BEVH = 200;
static constexpr int BEVW = 200;
static constexpr int HWB  = BEVH * BEVW;   // 40000

static constexpr int TPX  = 128;           // pixels (and threads) per scatter block
static constexpr int PIT  = 129;           // smem pitch (odd -> 2-way walk conflicts)

// Accumulator scratch: [b][bev_cell][channel] (channel contiguous)
__device__ float g_scratch[(size_t)B_ * HWB * C_];

__global__ void k_zero() {
    const int n4 = (B_ * HWB * C_) / 4;
    float4 z = make_float4(0.f, 0.f, 0.f, 0.f);
    float4* p = reinterpret_cast<float4*>(g_scratch);
    for (int i = blockIdx.x * blockDim.x + threadIdx.x; i < n4;
         i += gridDim.x * blockDim.x)
        p[i] = z;
}

__device__ __forceinline__ void red2(float* a, float x, float y) {
    asm volatile("red.global.add.v2.f32 [%0], {%1,%2};"
                 :: "l"(a), "f"(x), "f"(y) : "memory");
}

__global__ __launch_bounds__(TPX)
void k_scatter(const float* __restrict__ feat,
               const float* __restrict__ depth,
               const float* __restrict__ I_inv,
               const float* __restrict__ E_inv,
               const float* __restrict__ Vm) {
    __shared__ float  feat_s[C_ * PIT];     // [channel][pixel], pitch 129
    __shared__ float4 part_s[4][32];        // conf partials
    __shared__ float  conf_s[TPX];
    __shared__ float4 w_s[TPX];             // 4 corner weights per pixel
    __shared__ int4   idx_s[TPX];           // 4 corner cell indices per pixel

    const int t   = threadIdx.x;            // 0..127
    const int bn  = blockIdx.y;
    const int p0  = blockIdx.x * TPX;       // 175 * 128 == 22400

    // ---------- phase 1: depth conf partials + feat fill (coalesced) ----------
    const int pgrp = t & 31;                // 4-pixel group 0..31
    const int cq   = t >> 5;                // quarter 0..3
    {
        const float* dpb = depth + ((size_t)bn * D_ + cq * 16) * HWP + p0 + 4 * pgrp;
        float4 m = *reinterpret_cast<const float4*>(dpb);
        #pragma unroll
        for (int d = 1; d < 16; d++) {
            const float4 x = *reinterpret_cast<const float4*>(dpb + (size_t)d * HWP);
            m.x = fmaxf(m.x, x.x); m.y = fmaxf(m.y, x.y);
            m.z = fmaxf(m.z, x.z); m.w = fmaxf(m.w, x.w);
        }
        part_s[cq][pgrp] = m;

        const float* fb = feat + ((size_t)bn * C_ + cq * 16) * HWP + p0 + 4 * pgrp;
        #pragma unroll
        for (int j = 0; j < 16; j++) {
            const float4 f = *reinterpret_cast<const float4*>(fb + (size_t)j * HWP);
            float* row = feat_s + (cq * 16 + j) * PIT + 4 * pgrp;
            row[0] = f.x; row[1] = f.y; row[2] = f.z; row[3] = f.w;
        }
    }
    __syncthreads();

    if (t < 32) {
        float4 a = part_s[0][t], b2 = part_s[1][t];
        float4 c2 = part_s[2][t], d2 = part_s[3][t];
        conf_s[4 * t + 0] = fmaxf(fmaxf(a.x, b2.x), fmaxf(c2.x, d2.x));
        conf_s[4 * t + 1] = fmaxf(fmaxf(a.y, b2.y), fmaxf(c2.y, d2.y));
        conf_s[4 * t + 2] = fmaxf(fmaxf(a.z, b2.z), fmaxf(c2.z, d2.z));
        conf_s[4 * t + 3] = fmaxf(fmaxf(a.w, b2.w), fmaxf(c2.w, d2.w));
    }
    __syncthreads();

    // ---------- phase 2: geometry per pixel (bug-faithful width-outer grid) ----------
    {
        const int p = p0 + t;
        const float u = (float)(p / HF_);
        const float v = (float)(p % HF_);

        const float* Ii = I_inv + bn * 9;
        const float* Ei = E_inv + bn * 16;

        const float cx = Ii[0] * u + Ii[1] * v + Ii[2];
        const float cy = Ii[3] * u + Ii[4] * v + Ii[5];
        const float cz = Ii[6] * u + Ii[7] * v + Ii[8];

        const float tx = Ei[3], ty = Ei[7], tz = Ei[11];
        const float dx = Ei[0] * cx + Ei[1] * cy + Ei[2]  * cz + tx;
        const float dy = Ei[4] * cx + Ei[5] * cy + Ei[6]  * cz + ty;
        const float dz = Ei[8] * cx + Ei[9] * cy + Ei[10] * cz + tz;

        const float s  = -tz / fmaxf(dz, 1e-6f);
        const float ex = tx + dx * s;
        const float ey = ty + dy * s;

        const float q0 = Vm[0] * ex + Vm[1] * ey + Vm[2];
        const float q1 = Vm[3] * ex + Vm[4] * ey + Vm[5];
        const float q2 = Vm[6] * ex + Vm[7] * ey + Vm[8];
        const float zc = fmaxf(q2, 1e-7f);
        const float bevx = q0 / zc;
        const float bevy = q1 / zc;

        const float gx = bevx / (float)(BEVW - 1) * 2.f - 1.f;
        const float gy = bevy / (float)(BEVH - 1) * 2.f - 1.f;
        const float px = (gx + 1.f) * (float)(BEVW - 1) / 2.f;
        const float py = (gy + 1.f) * (float)(BEVH - 1) / 2.f;

        const float x0 = fminf(fmaxf(floorf(px), 0.f), (float)(BEVW - 1));
        const float y0 = fminf(fmaxf(floorf(py), 0.f), (float)(BEVH - 1));
        const float x1 = fminf(x0 + 1.f, (float)(BEVW - 1));
        const float y1 = fminf(y0 + 1.f, (float)(BEVH - 1));

        const float scale = conf_s[t] * (1.f / (float)N_);   // fold mean over n

        float4 w;
        w.x = (x1 - px) * (y1 - py) * scale;
        w.y = (px - x0) * (y1 - py) * scale;
        w.z = (x1 - px) * (py - y0) * scale;
        w.w = (px - x0) * (py - y0) * scale;
        w_s[t] = w;

        int4 id;
        id.x = (int)y0 * BEVW + (int)x0;
        id.y = (int)y0 * BEVW + (int)x1;
        id.z = (int)y1 * BEVW + (int)x0;
        id.w = (int)y1 * BEVW + (int)x1;
        idx_s[t] = id;
    }
    __syncthreads();

    // ---------- phase 3: serial walk, lane = channel pair, warp = 32 pixels ----------
    // i00 uniquely determines (x0,y0) => all 4 corner indices; contiguous
    // equal-i00 runs are accumulated in registers and flushed with one
    // warp-wide red.v2 per corner (covers all 64 channels).
    {
        const int wid  = t >> 5;            // warp 0..3 -> pixels 32w..32w+31
        const int lane = t & 31;
        const int c0   = 2 * lane;          // this lane's channel pair

        float* sb = g_scratch + (size_t)(bn / N_) * HWB * C_ + c0;
        const float* f0row = feat_s + (size_t)c0 * PIT;
        const float* f1row = feat_s + (size_t)(c0 + 1) * PIT;

        float a0 = 0.f, a1 = 0.f, a2 = 0.f, a3 = 0.f;   // corner accs, ch c0
        float b0 = 0.f, b1 = 0.f, b2 = 0.f, b3 = 0.f;   // corner accs, ch c0+1
        int4 pid = idx_s[wid * 32];         // first pixel's indices

        #pragma unroll 4
        for (int q = 0; q < 32; q++) {
            const int pq = wid * 32 + q;
            const int4   id = idx_s[pq];    // uniform in warp -> LDS broadcast
            const float4 w  = w_s[pq];      // uniform in warp

            if (id.x != pid.x) {            // warp-uniform branch
                red2(sb + (size_t)pid.x * C_, a0, b0);
                red2(sb + (size_t)pid.y * C_, a1, b1);
                red2(sb + (size_t)pid.z * C_, a2, b2);
                red2(sb + (size_t)pid.w * C_, a3, b3);
                a0 = a1 = a2 = a3 = 0.f;
                b0 = b1 = b2 = b3 = 0.f;
                pid = id;
            }
            const float f0 = f0row[pq];
            const float f1 = f1row[pq];
            a0 += w.x * f0;  b0 += w.x * f1;
            a1 += w.y * f0;  b1 += w.y * f1;
            a2 += w.z * f0;  b2 += w.z * f1;
            a3 += w.w * f0;  b3 += w.w * f1;
        }
        red2(sb + (size_t)pid.x * C_, a0, b0);
        red2(sb + (size_t)pid.y * C_, a1, b1);
        red2(sb + (size_t)pid.z * C_, a2, b2);
        red2(sb + (size_t)pid.w * C_, a3, b3);
    }
}

// scratch [b][cell][c] -> out [b][c][cell], 64x64 tiles, vectorized global I/O.
__global__ __launch_bounds__(256)
void k_transpose(float* __restrict__ out) {
    __shared__ float tile[C_][65];
    const int cellBase = blockIdx.x * 64;   // 40000 / 64 = 625 exact
    const int b        = blockIdx.y;
    const int t        = threadIdx.x;       // 0..255

    const float* src = g_scratch + (size_t)b * HWB * C_;
    const int cgrp = (t & 15) * 4;
    const int crow = t >> 4;                // 0..15
    #pragma unroll
    for (int r = 0; r < 4; r++) {
        const int cell = crow + 16 * r;
        const float4 f = *reinterpret_cast<const float4*>(
            src + (size_t)(cellBase + cell) * C_ + cgrp);
        tile[cgrp + 0][cell] = f.x;
        tile[cgrp + 1][cell] = f.y;
        tile[cgrp + 2][cell] = f.z;
        tile[cgrp + 3][cell] = f.w;
    }
    __syncthreads();
    #pragma unroll
    for (int r = 0; r < 4; r++) {
        const int ch = crow + 16 * r;
        const float4 o = make_float4(tile[ch][cgrp + 0], tile[ch][cgrp + 1],
                                     tile[ch][cgrp + 2], tile[ch][cgrp + 3]);
        *reinterpret_cast<float4*>(
            out + ((size_t)b * C_ + ch) * HWB + cellBase + cgrp) = o;
    }
}

extern "C" void kernel_launch(void* const* d_in, const int* in_sizes, int n_in,
                              void* d_out, int out_size) {
    const float* feat  = (const float*)d_in[0];
    const float* depth = (const float*)d_in[1];
    const float* I_inv = (const float*)d_in[2];
    const float* E_inv = (const float*)d_in[3];
    const float* Vm    = (const float*)d_in[4];
    float* out = (float*)d_out;

    k_zero<<<2560, 512>>>();               // scratch clean before scatter

    dim3 gs(HWP / TPX, B_ * N_);           // (175, 12)
    k_scatter<<<gs, TPX>>>(feat, depth, I_inv, E_inv, Vm);

    dim3 gt(HWB / 64, B_);                 // (625, 2)
    k_transpose<<<gt, 256>>>(out);
}

// round 14
// speedup vs baseline: 2.4187x; 1.1606x over previous
#include <cuda_runtime.h>

// LiftSplatBEV — fixed shapes
// feat_bn   : [12, 64, 112, 200] f32
// depth_prob: [12, 64, 112, 200] f32
// I_inv     : [2, 6, 3, 3] f32
// E_inv     : [2, 6, 4, 4] f32
// V         : [3, 3] f32
// out       : [2, 64, 200, 200] f32

static constexpr int B_   = 2;
static constexpr int N_   = 6;
static constexpr int C_   = 64;
static constexpr int HF_  = 112;
static constexpr int WF_  = 200;
static constexpr int D_   = 64;
static constexpr int HWP  = HF_ * WF_;     // 22400
static constexpr int BEVH = 200;
static constexpr int BEVW = 200;
static constexpr int HWB  = BEVH * BEVW;   // 40000

static constexpr int TPX  = 128;           // pixels (and threads) per scatter block
static constexpr int PIT  = 129;           // smem pitch (odd -> 2-way walk conflicts)

// Accumulator scratch: [b][bev_cell][channel] (channel contiguous).
// Zero at module load; k_transpose re-zeroes (vectorized) after reading, so
// "scratch is zero when k_scatter starts" holds across graph replays
// (proven correct in the round-11 bench).
__device__ float g_scratch[(size_t)B_ * HWB * C_];

__device__ __forceinline__ void red2(float* a, float x, float y) {
    asm volatile("red.global.add.v2.f32 [%0], {%1,%2};"
                 :: "l"(a), "f"(x), "f"(y) : "memory");
}

__global__ __launch_bounds__(TPX)
void k_scatter(const float* __restrict__ feat,
               const float* __restrict__ depth,
               const float* __restrict__ I_inv,
               const float* __restrict__ E_inv,
               const float* __restrict__ Vm) {
    __shared__ float  feat_s[C_ * PIT];     // [channel][pixel], pitch 129
    __shared__ float4 part_s[4][32];        // conf partials
    __shared__ float  conf_s[TPX];
    __shared__ float4 w_s[TPX];             // 4 corner weights per pixel
    __shared__ int4   idx_s[TPX];           // 4 corner cell indices per pixel

    const int t   = threadIdx.x;            // 0..127
    const int bn  = blockIdx.y;
    const int p0  = blockIdx.x * TPX;       // 175 * 128 == 22400

    // ---------- phase 1: depth conf partials + feat fill (coalesced) ----------
    const int pgrp = t & 31;                // 4-pixel group 0..31
    const int cq   = t >> 5;                // quarter 0..3
    {
        const float* dpb = depth + ((size_t)bn * D_ + cq * 16) * HWP + p0 + 4 * pgrp;
        float4 m = *reinterpret_cast<const float4*>(dpb);
        #pragma unroll
        for (int d = 1; d < 16; d++) {
            const float4 x = *reinterpret_cast<const float4*>(dpb + (size_t)d * HWP);
            m.x = fmaxf(m.x, x.x); m.y = fmaxf(m.y, x.y);
            m.z = fmaxf(m.z, x.z); m.w = fmaxf(m.w, x.w);
        }
        part_s[cq][pgrp] = m;

        const float* fb = feat + ((size_t)bn * C_ + cq * 16) * HWP + p0 + 4 * pgrp;
        #pragma unroll
        for (int j = 0; j < 16; j++) {
            const float4 f = *reinterpret_cast<const float4*>(fb + (size_t)j * HWP);
            float* row = feat_s + (cq * 16 + j) * PIT + 4 * pgrp;
            row[0] = f.x; row[1] = f.y; row[2] = f.z; row[3] = f.w;
        }
    }
    __syncthreads();

    if (t < 32) {
        float4 a = part_s[0][t], b2 = part_s[1][t];
        float4 c2 = part_s[2][t], d2 = part_s[3][t];
        conf_s[4 * t + 0] = fmaxf(fmaxf(a.x, b2.x), fmaxf(c2.x, d2.x));
        conf_s[4 * t + 1] = fmaxf(fmaxf(a.y, b2.y), fmaxf(c2.y, d2.y));
        conf_s[4 * t + 2] = fmaxf(fmaxf(a.z, b2.z), fmaxf(c2.z, d2.z));
        conf_s[4 * t + 3] = fmaxf(fmaxf(a.w, b2.w), fmaxf(c2.w, d2.w));
    }
    __syncthreads();

    // ---------- phase 2: geometry per pixel (bug-faithful width-outer grid) ----------
    {
        const int p = p0 + t;
        const float u = (float)(p / HF_);
        const float v = (float)(p % HF_);

        const float* Ii = I_inv + bn * 9;
        const float* Ei = E_inv + bn * 16;

        const float cx = Ii[0] * u + Ii[1] * v + Ii[2];
        const float cy = Ii[3] * u + Ii[4] * v + Ii[5];
        const float cz = Ii[6] * u + Ii[7] * v + Ii[8];

        const float tx = Ei[3], ty = Ei[7], tz = Ei[11];
        const float dx = Ei[0] * cx + Ei[1] * cy + Ei[2]  * cz + tx;
        const float dy = Ei[4] * cx + Ei[5] * cy + Ei[6]  * cz + ty;
        const float dz = Ei[8] * cx + Ei[9] * cy + Ei[10] * cz + tz;

        const float s  = -tz / fmaxf(dz, 1e-6f);
        const float ex = tx + dx * s;
        const float ey = ty + dy * s;

        const float q0 = Vm[0] * ex + Vm[1] * ey + Vm[2];
        const float q1 = Vm[3] * ex + Vm[4] * ey + Vm[5];
        const float q2 = Vm[6] * ex + Vm[7] * ey + Vm[8];
        const float zc = fmaxf(q2, 1e-7f);
        const float bevx = q0 / zc;
        const float bevy = q1 / zc;

        const float gx = bevx / (float)(BEVW - 1) * 2.f - 1.f;
        const float gy = bevy / (float)(BEVH - 1) * 2.f - 1.f;
        const float px = (gx + 1.f) * (float)(BEVW - 1) / 2.f;
        const float py = (gy + 1.f) * (float)(BEVH - 1) / 2.f;

        const float x0 = fminf(fmaxf(floorf(px), 0.f), (float)(BEVW - 1));
        const float y0 = fminf(fmaxf(floorf(py), 0.f), (float)(BEVH - 1));
        const float x1 = fminf(x0 + 1.f, (float)(BEVW - 1));
        const float y1 = fminf(y0 + 1.f, (float)(BEVH - 1));

        const float scale = conf_s[t] * (1.f / (float)N_);   // fold mean over n

        float4 w;
        w.x = (x1 - px) * (y1 - py) * scale;
        w.y = (px - x0) * (y1 - py) * scale;
        w.z = (x1 - px) * (py - y0) * scale;
        w.w = (px - x0) * (py - y0) * scale;
        w_s[t] = w;

        int4 id;
        id.x = (int)y0 * BEVW + (int)x0;
        id.y = (int)y0 * BEVW + (int)x1;
        id.z = (int)y1 * BEVW + (int)x0;
        id.w = (int)y1 * BEVW + (int)x1;
        idx_s[t] = id;
    }
    __syncthreads();

    // ---------- phase 3: serial walk, lane = channel pair, warp = 32 pixels ----------
    // i00 uniquely determines (x0,y0) => all 4 corner indices; contiguous
    // equal-i00 runs are accumulated in registers and flushed with one
    // warp-wide red.v2 per corner (covers all 64 channels).
    {
        const int wid  = t >> 5;            // warp 0..3 -> pixels 32w..32w+31
        const int lane = t & 31;
        const int c0   = 2 * lane;          // this lane's channel pair

        float* sb = g_scratch + (size_t)(bn / N_) * HWB * C_ + c0;
        const float* f0row = feat_s + (size_t)c0 * PIT;
        const float* f1row = feat_s + (size_t)(c0 + 1) * PIT;

        float a0 = 0.f, a1 = 0.f, a2 = 0.f, a3 = 0.f;   // corner accs, ch c0
        float b0 = 0.f, b1 = 0.f, b2 = 0.f, b3 = 0.f;   // corner accs, ch c0+1
        int4 pid = idx_s[wid * 32];         // first pixel's indices

        #pragma unroll 4
        for (int q = 0; q < 32; q++) {
            const int pq = wid * 32 + q;
            const int4   id = idx_s[pq];    // uniform in warp -> LDS broadcast
            const float4 w  = w_s[pq];      // uniform in warp

            if (id.x != pid.x) {            // warp-uniform branch
                red2(sb + (size_t)pid.x * C_, a0, b0);
                red2(sb + (size_t)pid.y * C_, a1, b1);
                red2(sb + (size_t)pid.z * C_, a2, b2);
                red2(sb + (size_t)pid.w * C_, a3, b3);
                a0 = a1 = a2 = a3 = 0.f;
                b0 = b1 = b2 = b3 = 0.f;
                pid = id;
            }
            const float f0 = f0row[pq];
            const float f1 = f1row[pq];
            a0 += w.x * f0;  b0 += w.x * f1;
            a1 += w.y * f0;  b1 += w.y * f1;
            a2 += w.z * f0;  b2 += w.z * f1;
            a3 += w.w * f0;  b3 += w.w * f1;
        }
        red2(sb + (size_t)pid.x * C_, a0, b0);
        red2(sb + (size_t)pid.y * C_, a1, b1);
        red2(sb + (size_t)pid.z * C_, a2, b2);
        red2(sb + (size_t)pid.w * C_, a3, b3);
    }
}

// scratch [b][cell][c] -> out [b][c][cell], 64x64 tiles.
// 128 threads, 8 independent LDG.128 per thread (front-batched for MLP),
// vectorized STG.128 out, vectorized rezero of scratch for the next replay.
__global__ __launch_bounds__(128)
void k_transpose(float* __restrict__ out) {
    __shared__ float tile[C_][65];
    const int cellBase = blockIdx.x * 64;   // 40000 / 64 = 625 exact
    const int b        = blockIdx.y;
    const int t        = threadIdx.x;       // 0..127

    float* src = g_scratch + (size_t)b * HWB * C_;
    const int cgrp = (t & 15) * 4;          // channel group 0,4,...,60
    const int crow = t >> 4;                // 0..7

    // front-batched loads: 8 independent LDG.128 in flight
    float4 f[8];
    #pragma unroll
    for (int r = 0; r < 8; r++) {
        const int cell = crow + 8 * r;
        f[r] = *reinterpret_cast<const float4*>(
            src + (size_t)(cellBase + cell) * C_ + cgrp);
    }
    // vectorized rezero (next replay's accumulator must start at 0)
    #pragma unroll
    for (int r = 0; r < 8; r++) {
        const int cell = crow + 8 * r;
        *reinterpret_cast<float4*>(src + (size_t)(cellBase + cell) * C_ + cgrp) =
            make_float4(0.f, 0.f, 0.f, 0.f);
    }
    #pragma unroll
    for (int r = 0; r < 8; r++) {
        const int cell = crow + 8 * r;
        tile[cgrp + 0][cell] = f[r].x;
        tile[cgrp + 1][cell] = f[r].y;
        tile[cgrp + 2][cell] = f[r].z;
        tile[cgrp + 3][cell] = f[r].w;
    }
    __syncthreads();

    #pragma unroll
    for (int r = 0; r < 8; r++) {
        const int ch = crow + 8 * r;
        const float4 o = make_float4(tile[ch][cgrp + 0], tile[ch][cgrp + 1],
                                     tile[ch][cgrp + 2], tile[ch][cgrp + 3]);
        *reinterpret_cast<float4*>(
            out + ((size_t)b * C_ + ch) * HWB + cellBase + cgrp) = o;
    }
}

extern "C" void kernel_launch(void* const* d_in, const int* in_sizes, int n_in,
                              void* d_out, int out_size) {
    const float* feat  = (const float*)d_in[0];
    const float* depth = (const float*)d_in[1];
    const float* I_inv = (const float*)d_in[2];
    const float* E_inv = (const float*)d_in[3];
    const float* Vm    = (const float*)d_in[4];
    float* out = (float*)d_out;

    dim3 gs(HWP / TPX, B_ * N_);           // (175, 12)
    k_scatter<<<gs, TPX>>>(feat, depth, I_inv, E_inv, Vm);

    dim3 gt(HWB / 64, B_);                 // (625, 2)
    k_transpose<<<gt, 128>>>(out);
}